// round 2
// baseline (speedup 1.0000x reference)
#include <cuda_runtime.h>
#include <float.h>

#define NN 50000
#define NE 1600000
#define NP 4096

// ---------------- scratch (device globals; no allocation allowed) ----------
__device__ float g_fni[NN * 32];     // h @ W_ni
__device__ float g_fnj[NN * 32];     // h @ W_nj + b_edge
__device__ float g_hh[NN * 128];     // h @ W_node   (H=4, ON=32)
__device__ float g_h[NN * 32];       // current node state
__device__ float g_logits[NE * 4];   // per-edge per-head logits, reused for z
__device__ float g_mx[NN * 4];       // segment max
__device__ float g_den[NN * 4];      // segment sum of exp
__device__ float g_agg[NN * 128];    // aggregated messages (N, H, ON)
__device__ float g_states[NN * 128]; // concat of 4 layer outputs (N, L*ON)

// ---------------- helpers ---------------------------------------------------
__device__ __forceinline__ void atomicMaxF(float* addr, float v) {
    // classic signed/unsigned trick; init value is -FLT_MAX (finite)
    if (v >= 0.0f)
        atomicMax((int*)addr, __float_as_int(v));
    else
        atomicMin((unsigned int*)addr, __float_as_uint(v));
}

// ---------------- kernels ---------------------------------------------------
__global__ void k_init() {
    int i = blockIdx.x * blockDim.x + threadIdx.x;
    if (i < NN * 128) g_agg[i] = 0.0f;
    if (i < NN * 4) { g_mx[i] = -FLT_MAX; g_den[i] = 0.0f; }
}

// fused node transforms: one warp per node row
__global__ void k_node(const float* __restrict__ x, int use_x,
                       const float* __restrict__ Wni,
                       const float* __restrict__ Wnj,
                       const float* __restrict__ be,
                       const float* __restrict__ Wnode) {
    __shared__ float sWni[32 * 32];
    __shared__ float sWnj[32 * 32];
    __shared__ float sWnode[32 * 128];
    __shared__ float sbe[32];
    int tid = threadIdx.x;
    for (int i = tid; i < 1024; i += blockDim.x) { sWni[i] = Wni[i]; sWnj[i] = Wnj[i]; }
    for (int i = tid; i < 4096; i += blockDim.x) sWnode[i] = Wnode[i];
    if (tid < 32) sbe[tid] = be[tid];
    __syncthreads();

    int warp = (blockIdx.x * blockDim.x + tid) >> 5;
    int ln = tid & 31;
    if (warp >= NN) return;

    const float* hin = use_x ? x : g_h;
    float hv = hin[warp * 32 + ln];
    float a0 = 0.f, a1 = 0.f, c0 = 0.f, c1 = 0.f, c2 = 0.f, c3 = 0.f;
#pragma unroll
    for (int k = 0; k < 32; k++) {
        float hk = __shfl_sync(0xffffffffu, hv, k);
        a0 += hk * sWni[k * 32 + ln];
        a1 += hk * sWnj[k * 32 + ln];
        c0 += hk * sWnode[k * 128 + ln];
        c1 += hk * sWnode[k * 128 + ln + 32];
        c2 += hk * sWnode[k * 128 + ln + 64];
        c3 += hk * sWnode[k * 128 + ln + 96];
    }
    g_fni[warp * 32 + ln] = a0;
    g_fnj[warp * 32 + ln] = a1 + sbe[ln];
    g_hh[warp * 128 + ln] = c0;
    g_hh[warp * 128 + ln + 32] = c1;
    g_hh[warp * 128 + ln + 64] = c2;
    g_hh[warp * 128 + ln + 96] = c3;
}

// per-edge logits + segment max: one warp per edge, lane = flat (head, oe)
__global__ void k_elog(const float* __restrict__ efeat,
                       const int* __restrict__ src,
                       const int* __restrict__ dst,
                       const float* __restrict__ Wf,
                       const float* __restrict__ attn) {
    __shared__ float sWf[256];
    __shared__ float sat[32];
    int tid = threadIdx.x;
    for (int i = tid; i < 256; i += blockDim.x) sWf[i] = Wf[i];
    if (tid < 32) sat[tid] = attn[tid];
    __syncthreads();

    int e = (blockIdx.x * blockDim.x + tid) >> 5;
    int ln = tid & 31;
    if (e >= NE) return;
    int s = src[e];
    int t = dst[e];
    float ev = (ln < 8) ? efeat[e * 8 + ln] : 0.0f;
    float f = g_fni[s * 32 + ln] + g_fnj[t * 32 + ln];
#pragma unroll
    for (int k = 0; k < 8; k++)
        f += __shfl_sync(0xffffffffu, ev, k) * sWf[k * 32 + ln];
    // leaky_relu (slope 0.01)
    f = (f > 0.0f) ? f : 0.01f * f;
    float p = f * sat[ln];
    p += __shfl_xor_sync(0xffffffffu, p, 1);
    p += __shfl_xor_sync(0xffffffffu, p, 2);
    p += __shfl_xor_sync(0xffffffffu, p, 4);
    if ((ln & 7) == 0) {
        int h = ln >> 3;
        g_logits[e * 4 + h] = p;
        atomicMaxF(&g_mx[t * 4 + h], p);
    }
}

// z = exp(logit - mx[dst]); accumulate denom
__global__ void k_eexp(const int* __restrict__ dst) {
    int i = blockIdx.x * blockDim.x + threadIdx.x;
    if (i >= NE * 4) return;
    int e = i >> 2, h = i & 3;
    int t = dst[e];
    float z = __expf(g_logits[i] - g_mx[t * 4 + h]);
    g_logits[i] = z;
    atomicAdd(&g_den[t * 4 + h], z);
}

// message scatter: warp per edge, lane handles float4 of hh row
__global__ void k_emsg(const int* __restrict__ src, const int* __restrict__ dst) {
    int tid = threadIdx.x;
    int e = (blockIdx.x * blockDim.x + tid) >> 5;
    int ln = tid & 31;
    if (e >= NE) return;
    int s = src[e];
    int t = dst[e];
    int h = ln >> 3;  // lane ln covers feats [ln*4, ln*4+4) -> head = ln/8
    float a = g_logits[e * 4 + h] / g_den[t * 4 + h];
    float4 v = reinterpret_cast<const float4*>(g_hh)[s * 32 + ln];
    float* base = &g_agg[t * 128 + ln * 4];
    atomicAdd(base + 0, v.x * a);
    atomicAdd(base + 1, v.y * a);
    atomicAdd(base + 2, v.z * a);
    atomicAdd(base + 3, v.w * a);
}

// head-sum + ELU -> next h, also write states slice
__global__ void k_nup(int l) {
    int i = blockIdx.x * blockDim.x + threadIdx.x;
    if (i >= NN * 32) return;
    int n = i >> 5, j = i & 31;
    const float* a = &g_agg[n * 128];
    float v = a[j] + a[32 + j] + a[64 + j] + a[96 + j];
    v = (v > 0.0f) ? v : (__expf(v) - 1.0f);  // ELU
    g_h[i] = v;
    g_states[n * 128 + l * 32 + j] = v;
}

// final pair MLP: block per pair, 128 threads
__global__ void k_mlp(const float* __restrict__ W1, const float* __restrict__ b1,
                      const float* __restrict__ W2, const float* __restrict__ b2,
                      const int* __restrict__ users, const int* __restrict__ items,
                      float* __restrict__ out) {
    __shared__ float zin[256];
    __shared__ float red[4];
    int b = blockIdx.x, j = threadIdx.x;
    int u = users[b], v = items[b];
    zin[j] = g_states[u * 128 + j];
    zin[j + 128] = g_states[v * 128 + j];
    __syncthreads();
    float acc = b1[j];
#pragma unroll 8
    for (int k = 0; k < 256; k++) acc += zin[k] * W1[k * 128 + j];
    acc = (acc > 0.0f) ? acc : 0.0f;
    float sres = acc * W2[j];
#pragma unroll
    for (int o = 16; o > 0; o >>= 1) sres += __shfl_xor_sync(0xffffffffu, sres, o);
    if ((j & 31) == 0) red[j >> 5] = sres;
    __syncthreads();
    if (j == 0) {
        float ssum = red[0] + red[1] + red[2] + red[3] + b2[0];
        out[b] = 1.0f / (1.0f + __expf(-ssum));
    }
}

// ---------------- launch ----------------------------------------------------
extern "C" void kernel_launch(void* const* d_in, const int* in_sizes, int n_in,
                              void* d_out, int out_size) {
    const float* x      = (const float*)d_in[0];
    const float* e      = (const float*)d_in[1];
    const float* W_ni   = (const float*)d_in[2];   // (4, 32, 32)
    const float* W_nj   = (const float*)d_in[3];   // (4, 32, 32)
    const float* W_fij  = (const float*)d_in[4];   // (4, 8, 32)
    const float* b_edge = (const float*)d_in[5];   // (4, 32)
    const float* attn   = (const float*)d_in[6];   // (4, 4, 8)
    const float* W_node = (const float*)d_in[7];   // (4, 32, 128)
    const float* W1     = (const float*)d_in[8];   // (256, 128)
    const float* b1     = (const float*)d_in[9];
    const float* W2     = (const float*)d_in[10];  // (128, 1)
    const float* b2     = (const float*)d_in[11];
    const int* src   = (const int*)d_in[12];
    const int* dst   = (const int*)d_in[13];
    const int* users = (const int*)d_in[14];
    const int* items = (const int*)d_in[15];
    float* out = (float*)d_out;

    const int T = 256;
    for (int l = 0; l < 4; l++) {
        k_init<<<(NN * 128 + T - 1) / T, T>>>();
        k_node<<<(NN * 32 + T - 1) / T, T>>>(x, l == 0 ? 1 : 0,
                                             W_ni + l * 1024, W_nj + l * 1024,
                                             b_edge + l * 32, W_node + l * 4096);
        k_elog<<<(NE * 32) / T, T>>>(e, src, dst, W_fij + l * 256, attn + l * 32);
        k_eexp<<<(NE * 4) / T, T>>>(dst);
        k_emsg<<<(NE * 32) / T, T>>>(src, dst);
        k_nup<<<(NN * 32 + T - 1) / T, T>>>(l);
    }
    k_mlp<<<NP, 128>>>(W1, b1, W2, b2, users, items, out);
}

// round 3
// speedup vs baseline: 1.6871x; 1.6871x over previous
#include <cuda_runtime.h>
#include <float.h>

#define NN 50000
#define NE 1600000
#define NP 4096

// ---------------- scratch (device globals; no allocation allowed) ----------
// pack: per-node [fni (32 floats) | hh (128 floats)] = 160 floats = 640B row
__device__ __align__(16) float g_pack[NN * 160];
__device__ __align__(16) float g_fnj[NN * 32];     // h @ W_nj + b_edge
__device__ float g_h[NN * 32];                     // current node state
__device__ __align__(16) float g_den[NN * 4];      // segment sum of exp
__device__ __align__(16) float g_agg[NN * 128];    // unnormalized messages (N, H, ON)
__device__ float g_states[NN * 128];               // concat of 4 layer outputs

// ---------------- kernels ---------------------------------------------------
__global__ void k_init() {
    int i = blockIdx.x * blockDim.x + threadIdx.x;
    if (i < NN * 128) g_agg[i] = 0.0f;
    if (i < NN * 4) g_den[i] = 0.0f;
}

// fused node transforms: one warp per node row
__global__ void k_node(const float* __restrict__ x, int use_x,
                       const float* __restrict__ Wni,
                       const float* __restrict__ Wnj,
                       const float* __restrict__ be,
                       const float* __restrict__ Wnode) {
    __shared__ float sWni[32 * 32];
    __shared__ float sWnj[32 * 32];
    __shared__ float sWnode[32 * 128];
    __shared__ float sbe[32];
    int tid = threadIdx.x;
    for (int i = tid; i < 1024; i += blockDim.x) { sWni[i] = Wni[i]; sWnj[i] = Wnj[i]; }
    for (int i = tid; i < 4096; i += blockDim.x) sWnode[i] = Wnode[i];
    if (tid < 32) sbe[tid] = be[tid];
    __syncthreads();

    int warp = (blockIdx.x * blockDim.x + tid) >> 5;
    int ln = tid & 31;
    if (warp >= NN) return;

    const float* hin = use_x ? x : g_h;
    float hv = hin[warp * 32 + ln];
    float a0 = 0.f, a1 = 0.f, c0 = 0.f, c1 = 0.f, c2 = 0.f, c3 = 0.f;
#pragma unroll
    for (int k = 0; k < 32; k++) {
        float hk = __shfl_sync(0xffffffffu, hv, k);
        a0 += hk * sWni[k * 32 + ln];
        a1 += hk * sWnj[k * 32 + ln];
        c0 += hk * sWnode[k * 128 + ln];
        c1 += hk * sWnode[k * 128 + ln + 32];
        c2 += hk * sWnode[k * 128 + ln + 64];
        c3 += hk * sWnode[k * 128 + ln + 96];
    }
    float* pk = g_pack + warp * 160;
    pk[ln] = a0;
    g_fnj[warp * 32 + ln] = a1 + sbe[ln];
    pk[32 + ln] = c0;
    pk[64 + ln] = c1;
    pk[96 + ln] = c2;
    pk[128 + ln] = c3;
}

// ONE fused edge pass: logits -> z=exp(logit) -> den += z -> agg += z*hh[src]
// (softmax max-shift dropped: shift-invariant, logits are O(1) so exp is safe)
__global__ void k_edge(const float* __restrict__ efeat,
                       const int* __restrict__ src,
                       const int* __restrict__ dst,
                       const float* __restrict__ Wf,
                       const float* __restrict__ attn) {
    __shared__ float sWf[256];
    __shared__ float sat[32];
    int tid = threadIdx.x;
    for (int i = tid; i < 256; i += blockDim.x) sWf[i] = Wf[i];
    if (tid < 32) sat[tid] = attn[tid];
    __syncthreads();

    int e = (blockIdx.x * blockDim.x + tid) >> 5;
    int ln = tid & 31;
    if (e >= NE) return;
    int s = src[e];
    int t = dst[e];
    const float* pk = g_pack + s * 160;

    float ev = (ln < 8) ? efeat[e * 8 + ln] : 0.0f;
    float f = pk[ln] + g_fnj[t * 32 + ln];
#pragma unroll
    for (int k = 0; k < 8; k++)
        f += __shfl_sync(0xffffffffu, ev, k) * sWf[k * 32 + ln];
    // leaky_relu (slope 0.01)
    f = (f > 0.0f) ? f : 0.01f * f;
    float p = f * sat[ln];
    p += __shfl_xor_sync(0xffffffffu, p, 1);
    p += __shfl_xor_sync(0xffffffffu, p, 2);
    p += __shfl_xor_sync(0xffffffffu, p, 4);
    float z = __expf(p);  // every lane of an 8-lane head group holds its head's z

    // den update: lane 0 gathers all 4 head z's, single v4 red
    if (ln == 0) {
        float z0 = z;
        float z1 = __shfl_sync(0xffffffffu, z, 8);
        float z2 = __shfl_sync(0xffffffffu, z, 16);
        float z3 = __shfl_sync(0xffffffffu, z, 24);
        asm volatile("red.global.add.v4.f32 [%0], {%1, %2, %3, %4};"
                     :: "l"(g_den + t * 4), "f"(z0), "f"(z1), "f"(z2), "f"(z3)
                     : "memory");
    } else {
        // keep shuffles convergent
        __shfl_sync(0xffffffffu, z, 8);
        __shfl_sync(0xffffffffu, z, 16);
        __shfl_sync(0xffffffffu, z, 24);
    }

    // message: lane ln covers feats [ln*4, ln*4+4), head = ln/8
    float4 v = reinterpret_cast<const float4*>(pk + 32)[ln];
    float* base = g_agg + t * 128 + ln * 4;
    asm volatile("red.global.add.v4.f32 [%0], {%1, %2, %3, %4};"
                 :: "l"(base), "f"(v.x * z), "f"(v.y * z), "f"(v.z * z), "f"(v.w * z)
                 : "memory");
}

// normalize by den, head-sum + ELU -> next h + states; reset agg/den in-place
__global__ void k_nup(int l) {
    int i = blockIdx.x * blockDim.x + threadIdx.x;
    if (i >= NN * 32) return;
    int n = i >> 5, j = i & 31;
    float* a = g_agg + n * 128;
    float* dn = g_den + n * 4;
    float d0 = dn[0], d1 = dn[1], d2 = dn[2], d3 = dn[3];
    float v = 0.0f;
    if (d0 > 0.0f) v += a[j] / d0;
    if (d1 > 0.0f) v += a[32 + j] / d1;
    if (d2 > 0.0f) v += a[64 + j] / d2;
    if (d3 > 0.0f) v += a[96 + j] / d3;
    // reset scratch for next layer (same warp owns this node; loads already done)
    a[j] = 0.0f; a[32 + j] = 0.0f; a[64 + j] = 0.0f; a[96 + j] = 0.0f;
    if (j < 4) dn[j] = 0.0f;
    v = (v > 0.0f) ? v : (__expf(v) - 1.0f);  // ELU
    g_h[i] = v;
    g_states[n * 128 + l * 32 + j] = v;
}

// final pair MLP: block per pair, 128 threads
__global__ void k_mlp(const float* __restrict__ W1, const float* __restrict__ b1,
                      const float* __restrict__ W2, const float* __restrict__ b2,
                      const int* __restrict__ users, const int* __restrict__ items,
                      float* __restrict__ out) {
    __shared__ float zin[256];
    __shared__ float red[4];
    int b = blockIdx.x, j = threadIdx.x;
    int u = users[b], v = items[b];
    zin[j] = g_states[u * 128 + j];
    zin[j + 128] = g_states[v * 128 + j];
    __syncthreads();
    float acc = b1[j];
#pragma unroll 8
    for (int k = 0; k < 256; k++) acc += zin[k] * W1[k * 128 + j];
    acc = (acc > 0.0f) ? acc : 0.0f;
    float sres = acc * W2[j];
#pragma unroll
    for (int o = 16; o > 0; o >>= 1) sres += __shfl_xor_sync(0xffffffffu, sres, o);
    if ((j & 31) == 0) red[j >> 5] = sres;
    __syncthreads();
    if (j == 0) {
        float ssum = red[0] + red[1] + red[2] + red[3] + b2[0];
        out[b] = 1.0f / (1.0f + __expf(-ssum));
    }
}

// ---------------- launch ----------------------------------------------------
extern "C" void kernel_launch(void* const* d_in, const int* in_sizes, int n_in,
                              void* d_out, int out_size) {
    const float* x      = (const float*)d_in[0];
    const float* e      = (const float*)d_in[1];
    const float* W_ni   = (const float*)d_in[2];   // (4, 32, 32)
    const float* W_nj   = (const float*)d_in[3];   // (4, 32, 32)
    const float* W_fij  = (const float*)d_in[4];   // (4, 8, 32)
    const float* b_edge = (const float*)d_in[5];   // (4, 32)
    const float* attn   = (const float*)d_in[6];   // (4, 4, 8)
    const float* W_node = (const float*)d_in[7];   // (4, 32, 128)
    const float* W1     = (const float*)d_in[8];   // (256, 128)
    const float* b1     = (const float*)d_in[9];
    const float* W2     = (const float*)d_in[10];  // (128, 1)
    const float* b2     = (const float*)d_in[11];
    const int* src   = (const int*)d_in[12];
    const int* dst   = (const int*)d_in[13];
    const int* users = (const int*)d_in[14];
    const int* items = (const int*)d_in[15];
    float* out = (float*)d_out;

    const int T = 256;
    k_init<<<(NN * 128 + T - 1) / T, T>>>();
    for (int l = 0; l < 4; l++) {
        k_node<<<(NN * 32 + T - 1) / T, T>>>(x, l == 0 ? 1 : 0,
                                             W_ni + l * 1024, W_nj + l * 1024,
                                             b_edge + l * 32, W_node + l * 4096);
        k_edge<<<(NE * 32) / T, T>>>(e, src, dst, W_fij + l * 256, attn + l * 32);
        k_nup<<<(NN * 32 + T - 1) / T, T>>>(l);
    }
    k_mlp<<<NP, 128>>>(W1, b1, W2, b2, users, items, out);
}

// round 4
// speedup vs baseline: 2.9587x; 1.7537x over previous
#include <cuda_runtime.h>
#include <float.h>

#define NN 50000
#define NE 1600000
#define NP 4096
#define FULL 0xffffffffu

// ---------------- scratch (device globals; no allocation allowed) ----------
// pack: per-node [fni (32) | h (32)] = 64 floats = 256B row
__device__ __align__(16) float g_pack[NN * 64];
__device__ __align__(16) float g_fnj[NN * 32];     // h @ W_nj + b_edge
__device__ __align__(16) float g_h[NN * 32];       // current node state
__device__ __align__(16) float g_agg[NN * 128];    // normalized per-head sums (N,H,32)
__device__ __align__(16) float g_states[NN * 128]; // concat of 4 layer outputs
// CSR preprocessing
__device__ int g_deg[NN];
__device__ int g_row[NN + 1];
__device__ int g_cur[NN];
__device__ int g_ssrc[NE];                          // src reordered by dst
__device__ __align__(16) float g_esort[NE * 8];     // edge feats reordered by dst

// ---------------- preprocessing (runs once per launch; graph-capturable) ----
__global__ void k_zero() {
    int i = blockIdx.x * blockDim.x + threadIdx.x;
    if (i < NN) g_deg[i] = 0;
}

__global__ void k_hist(const int* __restrict__ dst) {
    int i = blockIdx.x * blockDim.x + threadIdx.x;
    if (i < NE) atomicAdd(&g_deg[dst[i]], 1);
}

// single-block exclusive scan over 50000 degrees
__global__ void k_scan() {
    __shared__ int ssum[1024];
    int t = threadIdx.x;
    const int CH = (NN + 1023) / 1024;  // 49
    int start = t * CH;
    int end = min(start + CH, NN);
    int s = 0;
    for (int i = start; i < end; i++) s += g_deg[i];
    ssum[t] = s;
    __syncthreads();
    for (int off = 1; off < 1024; off <<= 1) {
        int v = (t >= off) ? ssum[t - off] : 0;
        __syncthreads();
        ssum[t] += v;
        __syncthreads();
    }
    int pre = (t > 0) ? ssum[t - 1] : 0;
    for (int i = start; i < end; i++) {
        g_row[i] = pre;
        g_cur[i] = pre;
        pre += g_deg[i];
    }
    if (t == 1023) g_row[NN] = pre;
}

__global__ void k_scatter(const int* __restrict__ src, const int* __restrict__ dst,
                          const float* __restrict__ efeat) {
    int e = blockIdx.x * blockDim.x + threadIdx.x;
    if (e >= NE) return;
    int pos = atomicAdd(&g_cur[dst[e]], 1);
    g_ssrc[pos] = src[e];
    const float4* er = (const float4*)(efeat + e * 8);
    float4* eo = (float4*)(g_esort + pos * 8);
    eo[0] = er[0];
    eo[1] = er[1];
}

// ---------------- per-layer kernels -----------------------------------------
// node transforms: fni, fnj, and copy h into pack. One warp per node.
__global__ void k_node(const float* __restrict__ x, int use_x,
                       const float* __restrict__ Wni,
                       const float* __restrict__ Wnj,
                       const float* __restrict__ be) {
    __shared__ float sWni[1024];
    __shared__ float sWnj[1024];
    __shared__ float sbe[32];
    int tid = threadIdx.x;
    for (int i = tid; i < 1024; i += blockDim.x) { sWni[i] = Wni[i]; sWnj[i] = Wnj[i]; }
    if (tid < 32) sbe[tid] = be[tid];
    __syncthreads();

    int warp = (blockIdx.x * blockDim.x + tid) >> 5;
    int ln = tid & 31;
    if (warp >= NN) return;

    const float* hin = use_x ? x : g_h;
    float hv = hin[warp * 32 + ln];
    float a0 = 0.f, a1 = 0.f;
#pragma unroll
    for (int k = 0; k < 32; k++) {
        float hk = __shfl_sync(FULL, hv, k);
        a0 += hk * sWni[k * 32 + ln];
        a1 += hk * sWnj[k * 32 + ln];
    }
    float* pk = g_pack + warp * 64;
    pk[ln] = a0;
    pk[32 + ln] = hv;
    g_fnj[warp * 32 + ln] = a1 + sbe[ln];
}

// CSR aggregation: one warp per dst node, NO atomics.
// Per in-edge: f = fni[src] + fnj[dst] + e@Wf + b -> leaky -> logit -> z=exp
// acc[head] += z * h[src]; den[head] += z. End: acc/den -> g_agg.
__global__ void k_edge(const float* __restrict__ Wf,
                       const float* __restrict__ attn) {
    __shared__ float sWf[256];
    __shared__ float sat[32];
    int tid = threadIdx.x;
    for (int i = tid; i < 256; i += blockDim.x) sWf[i] = Wf[i];
    if (tid < 32) sat[tid] = attn[tid];
    __syncthreads();

    int n = (blockIdx.x * blockDim.x + tid) >> 5;
    int ln = tid & 31;
    if (n >= NN) return;

    int base = g_row[n];
    int deg = g_row[n + 1] - base;
    float fnj_r = g_fnj[n * 32 + ln];
    float4 acc = make_float4(0.f, 0.f, 0.f, 0.f);
    float den = 0.f;
    int fs = (ln & 7) * 4;  // float4 slot within h row

#pragma unroll 2
    for (int i = 0; i < deg; i++) {
        int s = g_ssrc[base + i];
        float ev = (ln < 8) ? g_esort[(base + i) * 8 + ln] : 0.0f;
        const float* pk = g_pack + s * 64;
        float f = pk[ln] + fnj_r;
#pragma unroll
        for (int k = 0; k < 8; k++)
            f += __shfl_sync(FULL, ev, k) * sWf[k * 32 + ln];
        f = (f > 0.0f) ? f : 0.01f * f;  // leaky_relu
        float p = f * sat[ln];
        p += __shfl_xor_sync(FULL, p, 1);
        p += __shfl_xor_sync(FULL, p, 2);
        p += __shfl_xor_sync(FULL, p, 4);  // all 8 lanes of head group hold sum
        float z = __expf(p);
        den += z;
        float4 hv = *(const float4*)(pk + 32 + fs);
        acc.x += z * hv.x;
        acc.y += z * hv.y;
        acc.z += z * hv.z;
        acc.w += z * hv.w;
    }
    float inv = (den > 0.0f) ? 1.0f / den : 0.0f;
    acc.x *= inv; acc.y *= inv; acc.z *= inv; acc.w *= inv;
    // lane ln: head ln/8, feats (ln%8)*4 .. +4
    *(float4*)(g_agg + n * 128 + ln * 4) = acc;
}

// per-node epilogue: out = ELU( sum_h acc[h] @ W_node[:,h,:] ) -> g_h, g_states
__global__ void k_post(const float* __restrict__ Wnode, int l) {
    __shared__ float sWn[4096];
    extern __shared__ float sacc[];  // 128 floats per warp
    int tid = threadIdx.x;
    for (int i = tid; i < 4096; i += blockDim.x) sWn[i] = Wnode[i];
    __syncthreads();

    int wid = tid >> 5;
    int ln = tid & 31;
    int n = (blockIdx.x * blockDim.x + tid) >> 5;
    if (n >= NN) return;

    float* sa = sacc + wid * 128;
    float4 a4 = *(const float4*)(g_agg + n * 128 + ln * 4);
    int h = ln >> 3, k0 = (ln & 7) * 4;
    sa[h * 32 + k0 + 0] = a4.x;
    sa[h * 32 + k0 + 1] = a4.y;
    sa[h * 32 + k0 + 2] = a4.z;
    sa[h * 32 + k0 + 3] = a4.w;
    __syncwarp();

    float o = 0.0f;
#pragma unroll
    for (int hh = 0; hh < 4; hh++)
#pragma unroll
        for (int k = 0; k < 32; k++)
            o += sa[hh * 32 + k] * sWn[k * 128 + hh * 32 + ln];
    o = (o > 0.0f) ? o : (__expf(o) - 1.0f);  // ELU
    g_h[n * 32 + ln] = o;
    g_states[n * 128 + l * 32 + ln] = o;
}

// final pair MLP: block per pair, 128 threads
__global__ void k_mlp(const float* __restrict__ W1, const float* __restrict__ b1,
                      const float* __restrict__ W2, const float* __restrict__ b2,
                      const int* __restrict__ users, const int* __restrict__ items,
                      float* __restrict__ out) {
    __shared__ float zin[256];
    __shared__ float red[4];
    int b = blockIdx.x, j = threadIdx.x;
    int u = users[b], v = items[b];
    zin[j] = g_states[u * 128 + j];
    zin[j + 128] = g_states[v * 128 + j];
    __syncthreads();
    float acc = b1[j];
#pragma unroll 8
    for (int k = 0; k < 256; k++) acc += zin[k] * W1[k * 128 + j];
    acc = (acc > 0.0f) ? acc : 0.0f;
    float sres = acc * W2[j];
#pragma unroll
    for (int o = 16; o > 0; o >>= 1) sres += __shfl_xor_sync(FULL, sres, o);
    if ((j & 31) == 0) red[j >> 5] = sres;
    __syncthreads();
    if (j == 0) {
        float ssum = red[0] + red[1] + red[2] + red[3] + b2[0];
        out[b] = 1.0f / (1.0f + __expf(-ssum));
    }
}

// ---------------- launch ----------------------------------------------------
extern "C" void kernel_launch(void* const* d_in, const int* in_sizes, int n_in,
                              void* d_out, int out_size) {
    const float* x      = (const float*)d_in[0];
    const float* e      = (const float*)d_in[1];
    const float* W_ni   = (const float*)d_in[2];   // (4, 32, 32)
    const float* W_nj   = (const float*)d_in[3];   // (4, 32, 32)
    const float* W_fij  = (const float*)d_in[4];   // (4, 8, 32)
    const float* b_edge = (const float*)d_in[5];   // (4, 32)
    const float* attn   = (const float*)d_in[6];   // (4, 4, 8)
    const float* W_node = (const float*)d_in[7];   // (4, 32, 128)
    const float* W1     = (const float*)d_in[8];   // (256, 128)
    const float* b1     = (const float*)d_in[9];
    const float* W2     = (const float*)d_in[10];  // (128, 1)
    const float* b2     = (const float*)d_in[11];
    const int* src   = (const int*)d_in[12];
    const int* dst   = (const int*)d_in[13];
    const int* users = (const int*)d_in[14];
    const int* items = (const int*)d_in[15];
    float* out = (float*)d_out;

    const int T = 256;
    // one-time CSR build (per launch; src/dst constant)
    k_zero<<<(NN + T - 1) / T, T>>>();
    k_hist<<<(NE + T - 1) / T, T>>>(dst);
    k_scan<<<1, 1024>>>();
    k_scatter<<<(NE + T - 1) / T, T>>>(src, dst, e);

    for (int l = 0; l < 4; l++) {
        k_node<<<(NN * 32 + T - 1) / T, T>>>(x, l == 0 ? 1 : 0,
                                             W_ni + l * 1024, W_nj + l * 1024,
                                             b_edge + l * 32);
        k_edge<<<(NN * 32 + T - 1) / T, T>>>(W_fij + l * 256, attn + l * 32);
        k_post<<<(NN * 32 + T - 1) / T, T, 8 * 128 * sizeof(float)>>>(W_node + l * 4096, l);
    }
    k_mlp<<<NP, 128>>>(W1, b1, W2, b2, users, items, out);
}